// round 10
// baseline (speedup 1.0000x reference)
#include <cuda_runtime.h>

#define BB 32
#define LL 256
#define TT 1600
#define KK 80
#define PADV -1.0e12f

// ---- scratch (static device globals; no allocation) ----
__device__ float         g_lpT[BB * TT * LL];   // lp transposed [b][t][l]
__device__ float         g_A[BB * KK * LL];     // GEMM coeffs, k-major [b][k][l]
__device__ float         g_cst[BB * LL];        // per-(b,l) constant
__device__ unsigned      g_D[BB * TT * 8];      // Viterbi decision bits
__device__ unsigned char g_Dwrap[BB * TT];      // wrap bit (l=0 vs l=255) per column
__device__ int           g_path[BB * TT];       // chronological path rows (-1 = none)

// ============================================================
// K0: from mu_logvar [B][L][80] build GEMM coeffs + constant
// ============================================================
__global__ void __launch_bounds__(256) k_prep(const float* __restrict__ mlv) {
    int warp = threadIdx.x >> 5, lane = threadIdx.x & 31;
    int row = blockIdx.x * 8 + warp;           // [0, B*L)
    int b = row >> 8, l = row & 255;
    const float* p = mlv + row * 80;

    float mu = p[lane], lv = p[40 + lane];
    float iv = expf(-lv);
    g_A[(b * KK + lane) * LL + l]      = -0.0125f * iv;
    g_A[(b * KK + 40 + lane) * LL + l] =  0.025f  * mu * iv;
    float acc = mu * mu * iv + lv;
    if (lane < 8) {
        float mu2 = p[32 + lane], lv2 = p[72 + lane];
        float iv2 = expf(-lv2);
        g_A[(b * KK + 32 + lane) * LL + l] = -0.0125f * iv2;
        g_A[(b * KK + 72 + lane) * LL + l] =  0.025f  * mu2 * iv2;
        acc += mu2 * mu2 * iv2 + lv2;
    }
#pragma unroll
    for (int o = 16; o; o >>= 1) acc += __shfl_down_sync(0xffffffffu, acc, o);
    if (!lane) g_cst[row] = -0.0125f * acc;
}

// ============================================================
// K1: lp[b,l,t] = sum_k A[b,k,l]*Z[b,k,t] + cst[b,l], Z=[z^2;z]
//   128l x 64t tile, 8x4 register blocking (1.5 LDS-B per FFMA).
// ============================================================
__global__ void __launch_bounds__(256) k_lp(const float* __restrict__ z,
                                            float* __restrict__ out_lp) {
    extern __shared__ float sm[];
    float* As = sm;                 // [80][128]
    float* Zs = sm + 80 * 128;      // [80][64]
    int b = blockIdx.z;
    int l0 = blockIdx.y << 7, t0 = blockIdx.x << 6;
    int tid = threadIdx.x;

    for (int i = tid; i < 80 * 128; i += 256)
        As[i] = g_A[(b * KK + (i >> 7)) * LL + l0 + (i & 127)];
    for (int i = tid; i < 40 * 64; i += 256) {
        int c = i >> 6, t = i & 63;
        float zv = z[(b * 40 + c) * TT + t0 + t];
        Zs[c * 64 + t]        = zv * zv;
        Zs[(40 + c) * 64 + t] = zv;
    }
    __syncthreads();

    int tx = tid & 15, ty = tid >> 4;     // t = t0+tx*4+j, l = l0+ty*8+i
    float acc[8][4] = {};
#pragma unroll
    for (int k = 0; k < 80; k++) {
        float4 a0 = *(const float4*)&As[k * 128 + (ty << 3)];
        float4 a1 = *(const float4*)&As[k * 128 + (ty << 3) + 4];
        float4 zz = *(const float4*)&Zs[k * 64 + (tx << 2)];
        float av[8] = {a0.x, a0.y, a0.z, a0.w, a1.x, a1.y, a1.z, a1.w};
#pragma unroll
        for (int i = 0; i < 8; i++) {
            acc[i][0] += av[i] * zz.x; acc[i][1] += av[i] * zz.y;
            acc[i][2] += av[i] * zz.z; acc[i][3] += av[i] * zz.w;
        }
    }

    float cst[8];
#pragma unroll
    for (int i = 0; i < 8; i++) cst[i] = g_cst[b * LL + l0 + (ty << 3) + i];

#pragma unroll
    for (int i = 0; i < 8; i++) {
        int l = l0 + (ty << 3) + i;
        float4 v = make_float4(acc[i][0] + cst[i], acc[i][1] + cst[i],
                               acc[i][2] + cst[i], acc[i][3] + cst[i]);
        *(float4*)&out_lp[(size_t)(b * LL + l) * TT + t0 + (tx << 2)] = v;
    }
#pragma unroll
    for (int j = 0; j < 4; j++) {
        int t = t0 + (tx << 2) + j;
        float* dst = &g_lpT[(size_t)(b * TT + t) * LL + l0 + (ty << 3)];
        *(float4*)dst = make_float4(acc[0][j] + cst[0], acc[1][j] + cst[1],
                                    acc[2][j] + cst[2], acc[3][j] + cst[3]);
        *(float4*)(dst + 4) = make_float4(acc[4][j] + cst[4], acc[5][j] + cst[5],
                                          acc[6][j] + cst[6], acc[7][j] + cst[7]);
    }
}

// ============================================================
// K2: fused forward DP (logaddexp) + Viterbi DP (max).
//   TWO WARPS per batch, skewed pipeline (warp1 lags warp0 via a
//   volatile smem mailbox ring; dependency is one-directional).
//   Lane owns l = w*128 + lane*4 + k. Early stop at t = mlm1.
//   Wrap bit (l=0 vs l=255) computed by warp1 -> g_Dwrap.
// ============================================================
__device__ __forceinline__ void sts128v(unsigned addr, float x, float y, float z, float w) {
    asm volatile("st.volatile.shared.v4.f32 [%0], {%1,%2,%3,%4};"
                 :: "r"(addr), "f"(x), "f"(y), "f"(z), "f"(w));
}
__device__ __forceinline__ float4 lds128v(unsigned addr) {
    float4 r;
    asm volatile("ld.volatile.shared.v4.f32 {%0,%1,%2,%3}, [%4];"
                 : "=f"(r.x), "=f"(r.y), "=f"(r.z), "=f"(r.w) : "r"(addr));
    return r;
}
__device__ __forceinline__ float sel4(const float* a, int k) {
    float v = a[0];
#pragma unroll
    for (int i = 1; i < 4; i++) if (i == k) v = a[i];
    return v;
}

__global__ void __launch_bounds__(64) k_dp(const int* __restrict__ tl,
                                           const int* __restrict__ ml,
                                           float* __restrict__ out_loss) {
    __shared__ float4 ring[16];
    __shared__ int done1s;
    int b = blockIdx.x;
    int tid = threadIdx.x, w = tid >> 5, lane = tid & 31;
    const float* lp = g_lpT + (size_t)b * TT * LL;
    unsigned char* Db = ((unsigned char*)g_D) + (size_t)b * TT * 32;
    unsigned char* Dw = g_Dwrap + (size_t)b * TT;
    int mlm1 = ml[b] - 1, tlm1 = tl[b] - 1;
    int lbase = (w << 7) + (lane << 2);
    unsigned rb = (unsigned)__cvta_generic_to_shared(ring);
    volatile int* done1 = (volatile int*)&done1s;

    float a[4], bt[4];
#pragma unroll
    for (int k = 0; k < 4; k++) { a[k] = PADV; bt[k] = PADV; }
    float lp00 = lp[0];
    if (tid == 0) { a[0] = lp00; bt[0] = lp00; }

    int w_own = tlm1 >> 7, l_own = (tlm1 >> 2) & 31, k_own = tlm1 & 3;
    float rec = 0.f;
    if (mlm1 == 0 && w == w_own && lane == l_own) rec = sel4(a, k_own);

    if (tid == 0) *done1 = 0;
    if (w == 0) {                              // publish packet t=0
        float a127 = __shfl_sync(0xffffffffu, a[3], 31);
        float b127 = __shfl_sync(0xffffffffu, bt[3], 31);
        if (lane == 0) sts128v(rb, __int_as_float(0), a127, b127, bt[0]);
    }
    __syncthreads();

    float4 pf[8];
#pragma unroll
    for (int u = 0; u < 8; u++)
        pf[u] = (1 + u <= mlm1) ? *(const float4*)(lp + (size_t)(1 + u) * LL + lbase)
                                : make_float4(0.f, 0.f, 0.f, 0.f);

    for (int t0 = 1; t0 <= mlm1; t0 += 8) {
#pragma unroll
        for (int u = 0; u < 8; u++) {
            int t = t0 + u;
            if (t > mlm1) break;               // uniform within block

            if (w == 0 && (t & 7) == 1) {      // ring backpressure (rarely spins)
                if (lane == 0) { while (*done1 < t - 8) {} }
                __syncwarp();
            }
            float4 p = make_float4(0.f, 0.f, 0.f, 0.f);
            if (w == 1 && lane == 0) {         // wait for warp0's packet t-1
                unsigned ra = rb + (((t - 1) & 15) << 4);
                p = lds128v(ra);
                while (__float_as_int(p.x) != t - 1) p = lds128v(ra);
            }
            float b0old = __shfl_sync(0xffffffffu, p.w, 0);   // warp0's beta[0](t-1)
            float a3 = __shfl_up_sync(0xffffffffu, a[3], 1);
            float b3 = __shfl_up_sync(0xffffffffu, bt[3], 1);
            if (lane == 0) {
                a3 = (w == 1) ? p.y : PADV;    // alpha[l-1] boundary
                b3 = (w == 1) ? p.z : PADV;    // beta[l-1] boundary
            }

            // D nibbles from OLD beta (column t-1)
            unsigned nib = 0;
            nib |= (b3    > bt[0]) ? 1u : 0u;
            nib |= (bt[0] > bt[1]) ? 2u : 0u;
            nib |= (bt[1] > bt[2]) ? 4u : 0u;
            nib |= (bt[2] > bt[3]) ? 8u : 0u;
            if (w == 0 && lane == 0) nib &= ~1u;   // wrap bit lives in g_Dwrap
            unsigned hb = __shfl_down_sync(0xffffffffu, nib, 1);
            if (!(lane & 1))
                Db[(size_t)(t - 1) * 32 + (w << 4) + (lane >> 1)] =
                    (unsigned char)(nib | (hb << 4));
            if (w == 1 && lane == 31)
                Dw[t - 1] = (bt[3] > b0old) ? 1 : 0;   // beta[255] > beta[0]

            float4 c = pf[u];
            int tp = t + 8;
            if (tp <= mlm1) pf[u] = *(const float4*)(lp + (size_t)tp * LL + lbase);
            float lpv[4] = {c.x, c.y, c.z, c.w};

#pragma unroll
            for (int k = 3; k >= 0; k--) {
                float am1 = (k == 0) ? a3 : a[k - 1];
                float bm1 = (k == 0) ? b3 : bt[k - 1];
                float mx = fmaxf(a[k], am1);
                float e  = __expf(-fabsf(a[k] - am1));
                a[k]  = mx + __logf(1.f + e) + lpv[k] + 1e-7f;
                bt[k] = fmaxf(bt[k], bm1) + lpv[k];
            }

            if (w == 0) {                      // publish boundary packet t
                float a127 = __shfl_sync(0xffffffffu, a[3], 31);
                float b127 = __shfl_sync(0xffffffffu, bt[3], 31);
                if (lane == 0)
                    sts128v(rb + ((t & 15) << 4), __int_as_float(t), a127, b127, bt[0]);
            } else {
                if (lane == 0) *done1 = t;
            }
            if (t == mlm1 && w == w_own && lane == l_own) rec = sel4(a, k_own);
        }
    }
    if (w == w_own && lane == l_own) out_loss[b] = -rec / (float)(mlm1 + 1);
}

// ============================================================
// K3: backtrace, 16-step 64-bit register windows; wrap bit from
//   g_Dwrap when r==0. r=-1 absorbing (reference relu clamps).
// ============================================================
__global__ void __launch_bounds__(256) k_bt(const int* __restrict__ tl,
                                            const int* __restrict__ ml) {
    extern __shared__ unsigned char s3raw[];
    const int S = 1604;
    unsigned* Dsh = (unsigned*)s3raw;                          // [8][S]
    int* spath = (int*)(s3raw + 8 * S * 4);                    // TT ints
    unsigned char* wrap_sh = s3raw + 8 * S * 4 + TT * 4;       // TT bytes
    int b = blockIdx.x, tid = threadIdx.x;
    const unsigned* Dg = g_D + (size_t)b * TT * 8;
    const unsigned char* Dwg = g_Dwrap + (size_t)b * TT;
    for (int i = tid; i < TT * 8; i += 256)
        Dsh[(i & 7) * S + (i >> 3)] = Dg[i];
    for (int i = tid; i < TT; i += 256) { spath[i] = -1; wrap_sh[i] = Dwg[i]; }
    __syncthreads();

    if (tid == 0) {
        int mlm1v = ml[b] - 1;
        int r = tl[b] - 1;
        spath[mlm1v] = r;
        int k = 1;
        while (k <= mlm1v && r >= 0) {
            int whi = r >> 5;
            int wlo = (whi > 0) ? whi - 1 : 0;
            int basep = ((whi - 1) << 5);          // pos = r - basep in [1,63]
            int c0 = mlm1v - k;
            int nst = mlm1v - k + 1; if (nst > 16) nst = 16;
            unsigned hi[16], lo[16];
#pragma unroll
            for (int u = 0; u < 16; u++) {
                int col = c0 - u; if (col < 0) col = 0;
                hi[u] = Dsh[whi * S + col];
                lo[u] = Dsh[wlo * S + col];
            }
            bool done = false;
#pragma unroll
            for (int u = 0; u < 16; u++) {
                if (u >= nst) break;
                int col = c0 - u;
                int bit;
                if (r == 0) {
                    bit = wrap_sh[col];
                } else {
                    unsigned long long wq =
                        ((unsigned long long)hi[u] << 32) | (unsigned long long)lo[u];
                    bit = (int)((wq >> (unsigned)(r - basep)) & 1ull);
                }
                r -= bit;
                spath[col] = r;
                if (r < 0) { done = true; break; }
            }
            if (done) break;
            k += nst;
        }
    }
    __syncthreads();
    for (int i = tid; i < TT; i += 256) g_path[b * TT + i] = spath[i];
}

// ============================================================
// K4: alignment[b][t][l] = (l == path[b][t])  (warp per row)
// ============================================================
__global__ void __launch_bounds__(256) k_align(float* __restrict__ out_align) {
    int gw = (blockIdx.x * 256 + threadIdx.x) >> 5;   // = b*T + t
    int lane = threadIdx.x & 31;
    int p = g_path[gw];
    int base = lane << 3;
    float4 lo = make_float4((float)(p == base),     (float)(p == base + 1),
                            (float)(p == base + 2), (float)(p == base + 3));
    float4 hi = make_float4((float)(p == base + 4), (float)(p == base + 5),
                            (float)(p == base + 6), (float)(p == base + 7));
    float* o = out_align + ((size_t)gw << 8) + base;
    *(float4*)o       = lo;
    *(float4*)(o + 4) = hi;
}

extern "C" void kernel_launch(void* const* d_in, const int* in_sizes, int n_in,
                              void* d_out, int out_size) {
    const float* mlv = (const float*)d_in[0];
    const float* z   = (const float*)d_in[1];
    const int*   tl  = (const int*)d_in[2];
    const int*   ml  = (const int*)d_in[3];

    float* out       = (float*)d_out;
    float* out_loss  = out;                                   // [32]
    float* out_align = out + 32;                              // [32,1600,256]
    float* out_lp    = out + 32 + (size_t)BB * TT * LL;       // [32,256,1600]

    k_prep<<<(BB * LL) / 8, 256>>>(mlv);

    int smem_lp = (80 * 128 + 80 * 64) * 4;                   // 61440 B
    cudaFuncSetAttribute(k_lp, cudaFuncAttributeMaxDynamicSharedMemorySize, smem_lp);
    k_lp<<<dim3(TT / 64, LL / 128, BB), 256, smem_lp>>>(z, out_lp);

    k_dp<<<BB, 64>>>(tl, ml, out_loss);

    int smem_bt = 8 * 1604 * 4 + TT * 4 + TT;                 // 59328 B
    cudaFuncSetAttribute(k_bt, cudaFuncAttributeMaxDynamicSharedMemorySize, smem_bt);
    k_bt<<<BB, 256, smem_bt>>>(tl, ml);

    k_align<<<(BB * TT * 32) / 256, 256>>>(out_align);
}

// round 11
// speedup vs baseline: 1.1129x; 1.1129x over previous
#include <cuda_runtime.h>

#define BB 32
#define LL 256
#define TT 1600
#define KK 80
#define PADV -1.0e12f

// ---- scratch (static device globals; no allocation) ----
__device__ float    g_lpT[BB * TT * LL];     // lp transposed [b][t][l]
__device__ float    g_A[BB * KK * LL];       // GEMM coeffs, k-major [b][k][l]
__device__ float    g_cst[BB * LL];          // per-(b,l) constant
__device__ unsigned g_D[BB * TT * 8];        // Viterbi decision bits, 256/(b,t)
__device__ int      g_path[BB * TT];         // chronological path rows (-1 = none)
__device__ int      g_probe;                 // dummy sink for k_probe

// ============================================================
// probe: trivial launch to shift ncu's capture slot onto k_dp
// ============================================================
__global__ void k_probe() { g_probe = 1; }

// ============================================================
// K0: from mu_logvar [B][L][80] build GEMM coeffs + constant
// ============================================================
__global__ void __launch_bounds__(256) k_prep(const float* __restrict__ mlv) {
    int warp = threadIdx.x >> 5, lane = threadIdx.x & 31;
    int row = blockIdx.x * 8 + warp;           // [0, B*L)
    int b = row >> 8, l = row & 255;
    const float* p = mlv + row * 80;

    float mu = p[lane], lv = p[40 + lane];
    float iv = expf(-lv);
    g_A[(b * KK + lane) * LL + l]      = -0.0125f * iv;
    g_A[(b * KK + 40 + lane) * LL + l] =  0.025f  * mu * iv;
    float acc = mu * mu * iv + lv;
    if (lane < 8) {
        float mu2 = p[32 + lane], lv2 = p[72 + lane];
        float iv2 = expf(-lv2);
        g_A[(b * KK + 32 + lane) * LL + l] = -0.0125f * iv2;
        g_A[(b * KK + 72 + lane) * LL + l] =  0.025f  * mu2 * iv2;
        acc += mu2 * mu2 * iv2 + lv2;
    }
#pragma unroll
    for (int o = 16; o; o >>= 1) acc += __shfl_down_sync(0xffffffffu, acc, o);
    if (!lane) g_cst[row] = -0.0125f * acc;
}

// ============================================================
// K1: lp[b,l,t] = sum_k A[b,k,l] * Z[b,k,t] + cst[b,l], Z=[z^2;z]
//   64x64 tile, 4x4 register blocking; writes lp and lpT. (R7)
// ============================================================
__global__ void __launch_bounds__(256) k_lp(const float* __restrict__ z,
                                            float* __restrict__ out_lp) {
    __shared__ float As[80][64];
    __shared__ float Zs[80][64];
    int b = blockIdx.z;
    int l0 = blockIdx.y << 6, t0 = blockIdx.x << 6;
    int tid = threadIdx.x;

    for (int i = tid; i < 80 * 64; i += 256)
        As[i >> 6][i & 63] = g_A[(b * KK + (i >> 6)) * LL + l0 + (i & 63)];
    for (int i = tid; i < 40 * 64; i += 256) {
        int c = i >> 6, t = i & 63;
        float zv = z[(b * 40 + c) * TT + t0 + t];
        Zs[c][t] = zv * zv;
        Zs[40 + c][t] = zv;
    }
    __syncthreads();

    int tx = tid & 15, ty = tid >> 4;
    float acc[4][4] = {};
#pragma unroll
    for (int k = 0; k < 80; k++) {
        float4 a  = *(const float4*)&As[k][ty << 2];
        float4 zz = *(const float4*)&Zs[k][tx << 2];
        acc[0][0] += a.x * zz.x; acc[0][1] += a.x * zz.y; acc[0][2] += a.x * zz.z; acc[0][3] += a.x * zz.w;
        acc[1][0] += a.y * zz.x; acc[1][1] += a.y * zz.y; acc[1][2] += a.y * zz.z; acc[1][3] += a.y * zz.w;
        acc[2][0] += a.z * zz.x; acc[2][1] += a.z * zz.y; acc[2][2] += a.z * zz.z; acc[2][3] += a.z * zz.w;
        acc[3][0] += a.w * zz.x; acc[3][1] += a.w * zz.y; acc[3][2] += a.w * zz.z; acc[3][3] += a.w * zz.w;
    }

    float cst[4];
#pragma unroll
    for (int i = 0; i < 4; i++) cst[i] = g_cst[b * LL + l0 + (ty << 2) + i];

#pragma unroll
    for (int i = 0; i < 4; i++) {
        int l = l0 + (ty << 2) + i;
        float4 v = make_float4(acc[i][0] + cst[i], acc[i][1] + cst[i],
                               acc[i][2] + cst[i], acc[i][3] + cst[i]);
        *(float4*)&out_lp[(size_t)(b * LL + l) * TT + t0 + (tx << 2)] = v;
    }
#pragma unroll
    for (int j = 0; j < 4; j++) {
        int t = t0 + (tx << 2) + j;
        float4 v = make_float4(acc[0][j] + cst[0], acc[1][j] + cst[1],
                               acc[2][j] + cst[2], acc[3][j] + cst[3]);
        *(float4*)&g_lpT[(size_t)(b * TT + t) * LL + l0 + (ty << 2)] = v;
    }
}

// ============================================================
// K2: fused forward DP (alpha, logaddexp) + Viterbi DP (beta, max).
//   ONE WARP PER BATCH (R9) + EARLY STOP at t = mlm1.
//   Lane owns l = lane*8+k (blocked); k>0 stencil in registers,
//   k=0 via rotate-shfl (also provides (l-1)%256 wrap for D bits).
//   D bits: one byte per lane per column. Columns 0..mlm1-1 only
//   (the only ones the backtrace reads).
// ============================================================
__device__ __forceinline__ float sel8(const float* a, int k) {
    float v = a[0];
#pragma unroll
    for (int i = 1; i < 8; i++) if (i == k) v = a[i];
    return v;
}

__global__ void __launch_bounds__(32) k_dp(const int* __restrict__ tl,
                                           const int* __restrict__ ml,
                                           float* __restrict__ out_loss) {
    int b = blockIdx.x, lane = threadIdx.x;
    const float* lp = g_lpT + (size_t)b * TT * LL;
    unsigned char* Db = ((unsigned char*)g_D) + (size_t)b * TT * 32;
    int mlm1 = ml[b] - 1, tlm1 = tl[b] - 1;
    int rl = tlm1 >> 3, rk = tlm1 & 7;
    int src = (lane + 31) & 31;                 // rotate-up source lane

    float a[8], bt[8];
#pragma unroll
    for (int k = 0; k < 8; k++) { a[k] = PADV; bt[k] = PADV; }
    float lp00 = lp[0];
    if (lane == 0) { a[0] = lp00; bt[0] = lp00; }
    float rec = 0.f;
    if (mlm1 == 0 && lane == rl) rec = sel8(a, rk);

    // 8-deep lp prefetch (32B per lane per step, contiguous)
    float4 pf0[8], pf1[8];
#pragma unroll
    for (int u = 0; u < 8; u++) {
        if (1 + u <= mlm1) {
            const float4* p = (const float4*)(lp + (size_t)(1 + u) * LL + lane * 8);
            pf0[u] = p[0]; pf1[u] = p[1];
        } else {
            pf0[u] = make_float4(0.f, 0.f, 0.f, 0.f);
            pf1[u] = pf0[u];
        }
    }

    for (int t0 = 1; t0 <= mlm1; t0 += 8) {
#pragma unroll
        for (int u = 0; u < 8; u++) {
            int t = t0 + u;
            if (t > mlm1) break;                // uniform
            float4 c0 = pf0[u], c1 = pf1[u];
            int tp = t + 8;
            if (tp <= mlm1) {
                const float4* p = (const float4*)(lp + (size_t)tp * LL + lane * 8);
                pf0[u] = p[0]; pf1[u] = p[1];
            }
            float lpv[8] = {c0.x, c0.y, c0.z, c0.w, c1.x, c1.y, c1.z, c1.w};

            // boundary values from previous step (old registers)
            float aw = __shfl_sync(0xffffffffu, a[7], src);   // alpha[l-1]
            float bw = __shfl_sync(0xffffffffu, bt[7], src);  // beta[(l-1)%256]
            float am1_0 = (lane == 0) ? PADV : aw;
            float bm1_0 = (lane == 0) ? PADV : bw;

            // D bits for column t-1 (old beta, wrap semantics at l=0)
            unsigned by = (bw    > bt[0]) ? 1u   : 0u;
            by |= (bt[0] > bt[1]) ? 2u   : 0u;
            by |= (bt[1] > bt[2]) ? 4u   : 0u;
            by |= (bt[2] > bt[3]) ? 8u   : 0u;
            by |= (bt[3] > bt[4]) ? 16u  : 0u;
            by |= (bt[4] > bt[5]) ? 32u  : 0u;
            by |= (bt[5] > bt[6]) ? 64u  : 0u;
            by |= (bt[6] > bt[7]) ? 128u : 0u;
            Db[(size_t)(t - 1) * 32 + lane] = (unsigned char)by;

            // updates, descending k so a[k-1]/bt[k-1] are still old
#pragma unroll
            for (int k = 7; k >= 0; k--) {
                float am1 = (k == 0) ? am1_0 : a[k - 1];
                float bm1 = (k == 0) ? bm1_0 : bt[k - 1];
                float mx = fmaxf(a[k], am1);
                float e  = __expf(-fabsf(a[k] - am1));
                a[k]  = mx + __logf(1.f + e) + lpv[k] + 1e-7f;
                bt[k] = fmaxf(bt[k], bm1) + lpv[k];
            }
            if (t == mlm1 && lane == rl) rec = sel8(a, rk);
        }
    }
    if (lane == rl) out_loss[b] = -rec / (float)(mlm1 + 1);
}

// ============================================================
// K3: backtrace (R7 simple LDS-chain walk), bounded to k <= ml-1
//   with early exit once r < 0 (absorbing; writes stop anyway).
//   Reads D columns 0..ml-2 only.
// ============================================================
__global__ void __launch_bounds__(256) k_bt(const int* __restrict__ tl,
                                            const int* __restrict__ ml) {
    extern __shared__ unsigned char s3raw[];
    unsigned* Dsh = (unsigned*)s3raw;                 // TT*8 words
    int* spath = (int*)(s3raw + TT * 8 * 4);          // TT ints
    int b = blockIdx.x, tid = threadIdx.x;
    const unsigned* Dg = g_D + (size_t)b * TT * 8;
    for (int i = tid; i < TT * 8; i += 256) Dsh[i] = Dg[i];
    for (int i = tid; i < TT; i += 256) spath[i] = -1;
    __syncthreads();

    if (tid == 0) {
        int mlm1v = ml[b] - 1;
        int r = tl[b] - 1;
        spath[mlm1v] = r;                             // k=0 -> t = ml-1
        for (int k = 1; k <= mlm1v; k++) {
            unsigned w = Dsh[(mlm1v - k) * 8 + (r >> 5)];
            int go = (w >> (r & 31)) & 1;             // val_go > val_stay
            r -= go;
            if (r < 0) break;                         // absorbing, spath stays -1
            spath[mlm1v - k] = r;
        }
    }
    __syncthreads();
    for (int i = tid; i < TT; i += 256) g_path[b * TT + i] = spath[i];
}

// ============================================================
// K4: alignment[b][t][l] = (l == path[b][t])  (warp per row)
// ============================================================
__global__ void __launch_bounds__(256) k_align(float* __restrict__ out_align) {
    int gw = (blockIdx.x * 256 + threadIdx.x) >> 5;   // = b*T + t
    int lane = threadIdx.x & 31;
    int p = g_path[gw];
    int base = lane << 3;
    float4 lo = make_float4((float)(p == base),     (float)(p == base + 1),
                            (float)(p == base + 2), (float)(p == base + 3));
    float4 hi = make_float4((float)(p == base + 4), (float)(p == base + 5),
                            (float)(p == base + 6), (float)(p == base + 7));
    float* o = out_align + ((size_t)gw << 8) + base;
    *(float4*)o       = lo;
    *(float4*)(o + 4) = hi;
}

extern "C" void kernel_launch(void* const* d_in, const int* in_sizes, int n_in,
                              void* d_out, int out_size) {
    const float* mlv = (const float*)d_in[0];
    const float* z   = (const float*)d_in[1];
    const int*   tl  = (const int*)d_in[2];
    const int*   ml  = (const int*)d_in[3];

    float* out       = (float*)d_out;
    float* out_loss  = out;                                   // [32]
    float* out_align = out + 32;                              // [32,1600,256]
    float* out_lp    = out + 32 + (size_t)BB * TT * LL;       // [32,256,1600]

    k_prep<<<(BB * LL) / 8, 256>>>(mlv);
    k_probe<<<1, 1>>>();                                      // shifts ncu slot -> k_dp
    k_lp<<<dim3(TT / 64, LL / 64, BB), 256>>>(z, out_lp);
    k_dp<<<BB, 32>>>(tl, ml, out_loss);

    int smem_bt = TT * 8 * 4 + TT * 4;                        // 57600 B
    cudaFuncSetAttribute(k_bt, cudaFuncAttributeMaxDynamicSharedMemorySize, smem_bt);
    k_bt<<<BB, 256, smem_bt>>>(tl, ml);

    k_align<<<(BB * TT * 32) / 256, 256>>>(out_align);
}

// round 12
// speedup vs baseline: 1.1168x; 1.0035x over previous
#include <cuda_runtime.h>

#define BB 32
#define LL 256
#define TT 1600
#define KK 80
#define PADV -1.0e12f

// ---- scratch (static device globals; no allocation) ----
__device__ float    g_lpT[BB * TT * LL];     // lp transposed [b][t][l]
__device__ float    g_A[BB * KK * LL];       // GEMM coeffs, k-major [b][k][l]
__device__ float    g_cst[BB * LL];          // per-(b,l) constant
__device__ unsigned g_D[BB * TT * 8];        // Viterbi decision bits, 256/(b,t)
__device__ int      g_path[BB * TT];         // chronological path rows (-1 = none)
__device__ int      g_probe;                 // dummy sink for k_probe

// ============================================================
// probe: trivial launch so ncu's capture slot stays on k_dp
// ============================================================
__global__ void k_probe() { g_probe = 1; }

// ============================================================
// K0: from mu_logvar [B][L][80] build GEMM coeffs + constant
// ============================================================
__global__ void __launch_bounds__(256) k_prep(const float* __restrict__ mlv) {
    int warp = threadIdx.x >> 5, lane = threadIdx.x & 31;
    int row = blockIdx.x * 8 + warp;           // [0, B*L)
    int b = row >> 8, l = row & 255;
    const float* p = mlv + row * 80;

    float mu = p[lane], lv = p[40 + lane];
    float iv = expf(-lv);
    g_A[(b * KK + lane) * LL + l]      = -0.0125f * iv;
    g_A[(b * KK + 40 + lane) * LL + l] =  0.025f  * mu * iv;
    float acc = mu * mu * iv + lv;
    if (lane < 8) {
        float mu2 = p[32 + lane], lv2 = p[72 + lane];
        float iv2 = expf(-lv2);
        g_A[(b * KK + 32 + lane) * LL + l] = -0.0125f * iv2;
        g_A[(b * KK + 72 + lane) * LL + l] =  0.025f  * mu2 * iv2;
        acc += mu2 * mu2 * iv2 + lv2;
    }
#pragma unroll
    for (int o = 16; o; o >>= 1) acc += __shfl_down_sync(0xffffffffu, acc, o);
    if (!lane) g_cst[row] = -0.0125f * acc;
}

// ============================================================
// K1: lp[b,l,t] = sum_k A[b,k,l] * Z[b,k,t] + cst[b,l], Z=[z^2;z]
//   64x64 tile, 4x4 register blocking; writes lp and lpT. (R7)
// ============================================================
__global__ void __launch_bounds__(256) k_lp(const float* __restrict__ z,
                                            float* __restrict__ out_lp) {
    __shared__ float As[80][64];
    __shared__ float Zs[80][64];
    int b = blockIdx.z;
    int l0 = blockIdx.y << 6, t0 = blockIdx.x << 6;
    int tid = threadIdx.x;

    for (int i = tid; i < 80 * 64; i += 256)
        As[i >> 6][i & 63] = g_A[(b * KK + (i >> 6)) * LL + l0 + (i & 63)];
    for (int i = tid; i < 40 * 64; i += 256) {
        int c = i >> 6, t = i & 63;
        float zv = z[(b * 40 + c) * TT + t0 + t];
        Zs[c][t] = zv * zv;
        Zs[40 + c][t] = zv;
    }
    __syncthreads();

    int tx = tid & 15, ty = tid >> 4;
    float acc[4][4] = {};
#pragma unroll
    for (int k = 0; k < 80; k++) {
        float4 a  = *(const float4*)&As[k][ty << 2];
        float4 zz = *(const float4*)&Zs[k][tx << 2];
        acc[0][0] += a.x * zz.x; acc[0][1] += a.x * zz.y; acc[0][2] += a.x * zz.z; acc[0][3] += a.x * zz.w;
        acc[1][0] += a.y * zz.x; acc[1][1] += a.y * zz.y; acc[1][2] += a.y * zz.z; acc[1][3] += a.y * zz.w;
        acc[2][0] += a.z * zz.x; acc[2][1] += a.z * zz.y; acc[2][2] += a.z * zz.z; acc[2][3] += a.z * zz.w;
        acc[3][0] += a.w * zz.x; acc[3][1] += a.w * zz.y; acc[3][2] += a.w * zz.z; acc[3][3] += a.w * zz.w;
    }

    float cst[4];
#pragma unroll
    for (int i = 0; i < 4; i++) cst[i] = g_cst[b * LL + l0 + (ty << 2) + i];

#pragma unroll
    for (int i = 0; i < 4; i++) {
        int l = l0 + (ty << 2) + i;
        float4 v = make_float4(acc[i][0] + cst[i], acc[i][1] + cst[i],
                               acc[i][2] + cst[i], acc[i][3] + cst[i]);
        *(float4*)&out_lp[(size_t)(b * LL + l) * TT + t0 + (tx << 2)] = v;
    }
#pragma unroll
    for (int j = 0; j < 4; j++) {
        int t = t0 + (tx << 2) + j;
        float4 v = make_float4(acc[0][j] + cst[0], acc[1][j] + cst[1],
                               acc[2][j] + cst[2], acc[3][j] + cst[3]);
        *(float4*)&g_lpT[(size_t)(b * TT + t) * LL + l0 + (ty << 2)] = v;
    }
}

// ============================================================
// K2: DP, TWO INDEPENDENT WARPS per batch (zero sync):
//   warp0 = forward lse DP (alpha -> loss)    [MUFU-heavy]
//   warp1 = Viterbi max DP (beta -> D bits)   [ALU-only]
//   Lane owns l = lane*8+k (blocked). k>0 stencil in registers,
//   k=0 via rotate-shfl (also the (l-1)%256 wrap for D bits).
//   Early stop at t = mlm1. 4-deep lp prefetch.
// ============================================================
__device__ __forceinline__ float sel8(const float* a, int k) {
    float v = a[0];
#pragma unroll
    for (int i = 1; i < 8; i++) if (i == k) v = a[i];
    return v;
}

__global__ void __launch_bounds__(64) k_dp(const int* __restrict__ tl,
                                           const int* __restrict__ ml,
                                           float* __restrict__ out_loss) {
    int b = blockIdx.x;
    int w = threadIdx.x >> 5, lane = threadIdx.x & 31;
    const float* lp = g_lpT + (size_t)b * TT * LL;
    int mlm1 = ml[b] - 1;
    int src = (lane + 31) & 31;                 // rotate-up source lane

    if (w == 0) {
        // ---------------- alpha warp (loss) ----------------
        int tlm1 = tl[b] - 1;
        int rl = tlm1 >> 3, rk = tlm1 & 7;
        float a[8];
#pragma unroll
        for (int k = 0; k < 8; k++) a[k] = PADV;
        if (lane == 0) a[0] = lp[0];
        float rec = 0.f;
        if (mlm1 == 0 && lane == rl) rec = sel8(a, rk);

        float4 pf0[4], pf1[4];
#pragma unroll
        for (int u = 0; u < 4; u++) {
            if (1 + u <= mlm1) {
                const float4* p = (const float4*)(lp + (size_t)(1 + u) * LL + lane * 8);
                pf0[u] = p[0]; pf1[u] = p[1];
            } else {
                pf0[u] = make_float4(0.f, 0.f, 0.f, 0.f); pf1[u] = pf0[u];
            }
        }

        for (int t0 = 1; t0 <= mlm1; t0 += 4) {
#pragma unroll
            for (int u = 0; u < 4; u++) {
                int t = t0 + u;
                if (t > mlm1) break;            // warp-uniform
                float4 c0 = pf0[u], c1 = pf1[u];
                int tp = t + 4;
                if (tp <= mlm1) {
                    const float4* p = (const float4*)(lp + (size_t)tp * LL + lane * 8);
                    pf0[u] = p[0]; pf1[u] = p[1];
                }
                float lpv[8] = {c0.x, c0.y, c0.z, c0.w, c1.x, c1.y, c1.z, c1.w};

                float aw = __shfl_sync(0xffffffffu, a[7], src);
                float am1_0 = (lane == 0) ? PADV : aw;
#pragma unroll
                for (int k = 7; k >= 0; k--) {
                    float am1 = (k == 0) ? am1_0 : a[k - 1];
                    float mx = fmaxf(a[k], am1);
                    float e  = __expf(-fabsf(a[k] - am1));
                    a[k] = mx + __logf(1.f + e) + lpv[k] + 1e-7f;
                }
                if (t == mlm1 && lane == rl) rec = sel8(a, rk);
            }
        }
        if (lane == rl) out_loss[b] = -rec / (float)(mlm1 + 1);
    } else {
        // ---------------- beta warp (Viterbi D bits) ----------------
        unsigned char* Db = ((unsigned char*)g_D) + (size_t)b * TT * 32;
        float bt[8];
#pragma unroll
        for (int k = 0; k < 8; k++) bt[k] = PADV;
        if (lane == 0) bt[0] = lp[0];

        float4 pf0[4], pf1[4];
#pragma unroll
        for (int u = 0; u < 4; u++) {
            if (1 + u <= mlm1) {
                const float4* p = (const float4*)(lp + (size_t)(1 + u) * LL + lane * 8);
                pf0[u] = p[0]; pf1[u] = p[1];
            } else {
                pf0[u] = make_float4(0.f, 0.f, 0.f, 0.f); pf1[u] = pf0[u];
            }
        }

        for (int t0 = 1; t0 <= mlm1; t0 += 4) {
#pragma unroll
            for (int u = 0; u < 4; u++) {
                int t = t0 + u;
                if (t > mlm1) break;            // warp-uniform
                float4 c0 = pf0[u], c1 = pf1[u];
                int tp = t + 4;
                if (tp <= mlm1) {
                    const float4* p = (const float4*)(lp + (size_t)tp * LL + lane * 8);
                    pf0[u] = p[0]; pf1[u] = p[1];
                }
                float lpv[8] = {c0.x, c0.y, c0.z, c0.w, c1.x, c1.y, c1.z, c1.w};

                float bw = __shfl_sync(0xffffffffu, bt[7], src);  // beta[(l-1)%256]
                float bm1_0 = (lane == 0) ? PADV : bw;

                // D bits for column t-1 (old beta, wrap semantics at l=0)
                unsigned by = (bw    > bt[0]) ? 1u   : 0u;
                by |= (bt[0] > bt[1]) ? 2u   : 0u;
                by |= (bt[1] > bt[2]) ? 4u   : 0u;
                by |= (bt[2] > bt[3]) ? 8u   : 0u;
                by |= (bt[3] > bt[4]) ? 16u  : 0u;
                by |= (bt[4] > bt[5]) ? 32u  : 0u;
                by |= (bt[5] > bt[6]) ? 64u  : 0u;
                by |= (bt[6] > bt[7]) ? 128u : 0u;
                Db[(size_t)(t - 1) * 32 + lane] = (unsigned char)by;

#pragma unroll
                for (int k = 7; k >= 0; k--) {
                    float bm1 = (k == 0) ? bm1_0 : bt[k - 1];
                    bt[k] = fmaxf(bt[k], bm1) + lpv[k];
                }
            }
        }
    }
}

// ============================================================
// K3: backtrace (R7 simple LDS-chain walk), bounded to k <= ml-1
//   with early exit once r < 0 (absorbing; writes stop anyway).
// ============================================================
__global__ void __launch_bounds__(256) k_bt(const int* __restrict__ tl,
                                            const int* __restrict__ ml) {
    extern __shared__ unsigned char s3raw[];
    unsigned* Dsh = (unsigned*)s3raw;                 // TT*8 words
    int* spath = (int*)(s3raw + TT * 8 * 4);          // TT ints
    int b = blockIdx.x, tid = threadIdx.x;
    const unsigned* Dg = g_D + (size_t)b * TT * 8;
    for (int i = tid; i < TT * 8; i += 256) Dsh[i] = Dg[i];
    for (int i = tid; i < TT; i += 256) spath[i] = -1;
    __syncthreads();

    if (tid == 0) {
        int mlm1v = ml[b] - 1;
        int r = tl[b] - 1;
        spath[mlm1v] = r;                             // k=0 -> t = ml-1
        for (int k = 1; k <= mlm1v; k++) {
            unsigned w = Dsh[(mlm1v - k) * 8 + (r >> 5)];
            int go = (w >> (r & 31)) & 1;             // val_go > val_stay
            r -= go;
            if (r < 0) break;                         // absorbing, spath stays -1
            spath[mlm1v - k] = r;
        }
    }
    __syncthreads();
    for (int i = tid; i < TT; i += 256) g_path[b * TT + i] = spath[i];
}

// ============================================================
// K4: alignment[b][t][l] = (l == path[b][t])  (warp per row)
// ============================================================
__global__ void __launch_bounds__(256) k_align(float* __restrict__ out_align) {
    int gw = (blockIdx.x * 256 + threadIdx.x) >> 5;   // = b*T + t
    int lane = threadIdx.x & 31;
    int p = g_path[gw];
    int base = lane << 3;
    float4 lo = make_float4((float)(p == base),     (float)(p == base + 1),
                            (float)(p == base + 2), (float)(p == base + 3));
    float4 hi = make_float4((float)(p == base + 4), (float)(p == base + 5),
                            (float)(p == base + 6), (float)(p == base + 7));
    float* o = out_align + ((size_t)gw << 8) + base;
    *(float4*)o       = lo;
    *(float4*)(o + 4) = hi;
}

extern "C" void kernel_launch(void* const* d_in, const int* in_sizes, int n_in,
                              void* d_out, int out_size) {
    const float* mlv = (const float*)d_in[0];
    const float* z   = (const float*)d_in[1];
    const int*   tl  = (const int*)d_in[2];
    const int*   ml  = (const int*)d_in[3];

    float* out       = (float*)d_out;
    float* out_loss  = out;                                   // [32]
    float* out_align = out + 32;                              // [32,1600,256]
    float* out_lp    = out + 32 + (size_t)BB * TT * LL;       // [32,256,1600]

    k_prep<<<(BB * LL) / 8, 256>>>(mlv);
    k_probe<<<1, 1>>>();                                      // keeps ncu slot on k_dp
    k_lp<<<dim3(TT / 64, LL / 64, BB), 256>>>(z, out_lp);
    k_dp<<<BB, 64>>>(tl, ml, out_loss);

    int smem_bt = TT * 8 * 4 + TT * 4;                        // 57600 B
    cudaFuncSetAttribute(k_bt, cudaFuncAttributeMaxDynamicSharedMemorySize, smem_bt);
    k_bt<<<BB, 256, smem_bt>>>(tl, ml);

    k_align<<<(BB * TT * 32) / 256, 256>>>(out_align);
}

// round 15
// speedup vs baseline: 2.7692x; 2.4796x over previous
#include <cuda_runtime.h>

#define BB 32
#define LL 256
#define TT 1600
#define KK 80
#define PADV -1.0e12f

// ---- scratch (static device globals; no allocation) ----
__device__ float    g_lpT[BB * TT * LL];     // lp transposed [b][t][l]
__device__ float    g_A[BB * KK * LL];       // GEMM coeffs, k-major [b][k][l]
__device__ float    g_cst[BB * LL];          // per-(b,l) constant
__device__ unsigned g_D[BB * TT * 8];        // Viterbi decision bits, 256/(b,t)
__device__ int      g_path[BB * TT];         // chronological path rows (-1 = none)
__device__ int      g_probe;                 // dummy sink for k_probe

// ============================================================
// probe: trivial launch so ncu's capture slot stays on k_dp
// ============================================================
__global__ void k_probe() { g_probe = 1; }

// ============================================================
// K0: from mu_logvar [B][L][80] build GEMM coeffs + constant
// ============================================================
__global__ void __launch_bounds__(256) k_prep(const float* __restrict__ mlv) {
    int warp = threadIdx.x >> 5, lane = threadIdx.x & 31;
    int row = blockIdx.x * 8 + warp;           // [0, B*L)
    int b = row >> 8, l = row & 255;
    const float* p = mlv + row * 80;

    float mu = p[lane], lv = p[40 + lane];
    float iv = expf(-lv);
    g_A[(b * KK + lane) * LL + l]      = -0.0125f * iv;
    g_A[(b * KK + 40 + lane) * LL + l] =  0.025f  * mu * iv;
    float acc = mu * mu * iv + lv;
    if (lane < 8) {
        float mu2 = p[32 + lane], lv2 = p[72 + lane];
        float iv2 = expf(-lv2);
        g_A[(b * KK + 32 + lane) * LL + l] = -0.0125f * iv2;
        g_A[(b * KK + 72 + lane) * LL + l] =  0.025f  * mu2 * iv2;
        acc += mu2 * mu2 * iv2 + lv2;
    }
#pragma unroll
    for (int o = 16; o; o >>= 1) acc += __shfl_down_sync(0xffffffffu, acc, o);
    if (!lane) g_cst[row] = -0.0125f * acc;
}

// ============================================================
// K1: lp[b,l,t] = sum_k A[b,k,l] * Z[b,k,t] + cst[b,l], Z=[z^2;z]
//   64x64 tile, 4x4 register blocking; writes lp and lpT. (R7)
// ============================================================
__global__ void __launch_bounds__(256) k_lp(const float* __restrict__ z,
                                            float* __restrict__ out_lp) {
    __shared__ float As[80][64];
    __shared__ float Zs[80][64];
    int b = blockIdx.z;
    int l0 = blockIdx.y << 6, t0 = blockIdx.x << 6;
    int tid = threadIdx.x;

    for (int i = tid; i < 80 * 64; i += 256)
        As[i >> 6][i & 63] = g_A[(b * KK + (i >> 6)) * LL + l0 + (i & 63)];
    for (int i = tid; i < 40 * 64; i += 256) {
        int c = i >> 6, t = i & 63;
        float zv = z[(b * 40 + c) * TT + t0 + t];
        Zs[c][t] = zv * zv;
        Zs[40 + c][t] = zv;
    }
    __syncthreads();

    int tx = tid & 15, ty = tid >> 4;
    float acc[4][4] = {};
#pragma unroll
    for (int k = 0; k < 80; k++) {
        float4 a  = *(const float4*)&As[k][ty << 2];
        float4 zz = *(const float4*)&Zs[k][tx << 2];
        acc[0][0] += a.x * zz.x; acc[0][1] += a.x * zz.y; acc[0][2] += a.x * zz.z; acc[0][3] += a.x * zz.w;
        acc[1][0] += a.y * zz.x; acc[1][1] += a.y * zz.y; acc[1][2] += a.y * zz.z; acc[1][3] += a.y * zz.w;
        acc[2][0] += a.z * zz.x; acc[2][1] += a.z * zz.y; acc[2][2] += a.z * zz.z; acc[2][3] += a.z * zz.w;
        acc[3][0] += a.w * zz.x; acc[3][1] += a.w * zz.y; acc[3][2] += a.w * zz.z; acc[3][3] += a.w * zz.w;
    }

    float cst[4];
#pragma unroll
    for (int i = 0; i < 4; i++) cst[i] = g_cst[b * LL + l0 + (ty << 2) + i];

#pragma unroll
    for (int i = 0; i < 4; i++) {
        int l = l0 + (ty << 2) + i;
        float4 v = make_float4(acc[i][0] + cst[i], acc[i][1] + cst[i],
                               acc[i][2] + cst[i], acc[i][3] + cst[i]);
        *(float4*)&out_lp[(size_t)(b * LL + l) * TT + t0 + (tx << 2)] = v;
    }
#pragma unroll
    for (int j = 0; j < 4; j++) {
        int t = t0 + (tx << 2) + j;
        float4 v = make_float4(acc[0][j] + cst[0], acc[1][j] + cst[1],
                               acc[2][j] + cst[2], acc[3][j] + cst[3]);
        *(float4*)&g_lpT[(size_t)(b * TT + t) * LL + l0 + (ty << 2)] = v;
    }
}

// ============================================================
// K2: DP, two independent warps per batch, BRANCHLESS steady state.
//   warp0 = forward lse DP (alpha -> loss)
//   warp1 = Viterbi max DP (beta -> D bits)
//   Time loop: full chunks of 8 with zero conditionals; prefetch
//   address clamped with min(); remainder loop after; record read
//   from live registers after the loop (it ends exactly at mlm1).
// ============================================================
__device__ __forceinline__ float sel8(const float* a, int k) {
    float v = a[0];
#pragma unroll
    for (int i = 1; i < 8; i++) if (i == k) v = a[i];
    return v;
}

__global__ void __launch_bounds__(64) k_dp(const int* __restrict__ tl,
                                           const int* __restrict__ ml,
                                           float* __restrict__ out_loss) {
    int b = blockIdx.x;
    int w = threadIdx.x >> 5, lane = threadIdx.x & 31;
    const float* lp = g_lpT + (size_t)b * TT * LL + (lane << 3);
    int mlm1 = ml[b] - 1;
    int src = (lane + 31) & 31;                 // rotate-up source lane
    int nfull = mlm1 >> 3, rem = mlm1 & 7;

    if (w == 0) {
        // ---------------- alpha warp (loss) ----------------
        int tlm1 = tl[b] - 1;
        int rl = tlm1 >> 3, rk = tlm1 & 7;
        float a[8];
#pragma unroll
        for (int k = 0; k < 8; k++) a[k] = PADV;
        if (lane == 0) a[0] = __ldg(g_lpT + (size_t)b * TT * LL);

        float4 pf0[8], pf1[8];
#pragma unroll
        for (int u = 0; u < 8; u++) {           // preload t = 1..8 (clamped)
            int tc = min(1 + u, TT - 1);
            const float4* p = (const float4*)(lp + (size_t)tc * LL);
            pf0[u] = p[0]; pf1[u] = p[1];
        }

        for (int c = 0; c < nfull; c++) {
            int tb = 1 + (c << 3);
#pragma unroll
            for (int u = 0; u < 8; u++) {       // NO conditionals
                float4 c0 = pf0[u], c1 = pf1[u];
                int tp = min(tb + u + 8, TT - 1);
                const float4* p = (const float4*)(lp + (size_t)tp * LL);
                pf0[u] = p[0]; pf1[u] = p[1];
                float lpe[8] = {c0.x + 1e-7f, c0.y + 1e-7f, c0.z + 1e-7f, c0.w + 1e-7f,
                                c1.x + 1e-7f, c1.y + 1e-7f, c1.z + 1e-7f, c1.w + 1e-7f};
                float aw = __shfl_sync(0xffffffffu, a[7], src);
                float am1_0 = (lane == 0) ? PADV : aw;
#pragma unroll
                for (int k = 7; k >= 0; k--) {
                    float am1 = (k == 0) ? am1_0 : a[k - 1];
                    float mx = fmaxf(a[k], am1);
                    float e  = __expf(-fabsf(a[k] - am1));
                    a[k] = mx + (__logf(1.f + e) + lpe[k]);
                }
            }
        }
        for (int u = 0; u < rem; u++) {         // <=7 iterations
            float4 c0 = pf0[u], c1 = pf1[u];
            float lpe[8] = {c0.x + 1e-7f, c0.y + 1e-7f, c0.z + 1e-7f, c0.w + 1e-7f,
                            c1.x + 1e-7f, c1.y + 1e-7f, c1.z + 1e-7f, c1.w + 1e-7f};
            float aw = __shfl_sync(0xffffffffu, a[7], src);
            float am1_0 = (lane == 0) ? PADV : aw;
#pragma unroll
            for (int k = 7; k >= 0; k--) {
                float am1 = (k == 0) ? am1_0 : a[k - 1];
                float mx = fmaxf(a[k], am1);
                float e  = __expf(-fabsf(a[k] - am1));
                a[k] = mx + (__logf(1.f + e) + lpe[k]);
            }
        }
        // loop ended exactly at t = mlm1: live registers are the record
        float rec = sel8(a, rk);
        if (lane == rl) out_loss[b] = -rec / (float)(mlm1 + 1);
    } else {
        // ---------------- beta warp (Viterbi D bits) ----------------
        unsigned char* Db = ((unsigned char*)g_D) + (size_t)b * TT * 32 + lane;
        float bt[8];
#pragma unroll
        for (int k = 0; k < 8; k++) bt[k] = PADV;
        if (lane == 0) bt[0] = __ldg(g_lpT + (size_t)b * TT * LL);

        float4 pf0[8], pf1[8];
#pragma unroll
        for (int u = 0; u < 8; u++) {
            int tc = min(1 + u, TT - 1);
            const float4* p = (const float4*)(lp + (size_t)tc * LL);
            pf0[u] = p[0]; pf1[u] = p[1];
        }

        for (int c = 0; c < nfull; c++) {
            int tb = 1 + (c << 3);
#pragma unroll
            for (int u = 0; u < 8; u++) {       // NO conditionals
                float4 c0 = pf0[u], c1 = pf1[u];
                int tp = min(tb + u + 8, TT - 1);
                const float4* p = (const float4*)(lp + (size_t)tp * LL);
                pf0[u] = p[0]; pf1[u] = p[1];
                float lpv[8] = {c0.x, c0.y, c0.z, c0.w, c1.x, c1.y, c1.z, c1.w};

                float bw = __shfl_sync(0xffffffffu, bt[7], src);
                float bm1_0 = (lane == 0) ? PADV : bw;

                unsigned by = (bw    > bt[0]) ? 1u   : 0u;
                by |= (bt[0] > bt[1]) ? 2u   : 0u;
                by |= (bt[1] > bt[2]) ? 4u   : 0u;
                by |= (bt[2] > bt[3]) ? 8u   : 0u;
                by |= (bt[3] > bt[4]) ? 16u  : 0u;
                by |= (bt[4] > bt[5]) ? 32u  : 0u;
                by |= (bt[5] > bt[6]) ? 64u  : 0u;
                by |= (bt[6] > bt[7]) ? 128u : 0u;
                Db[(size_t)(tb + u - 1) * 32] = (unsigned char)by;

#pragma unroll
                for (int k = 7; k >= 0; k--) {
                    float bm1 = (k == 0) ? bm1_0 : bt[k - 1];
                    bt[k] = fmaxf(bt[k], bm1) + lpv[k];
                }
            }
        }
        int tb = 1 + (nfull << 3);
        for (int u = 0; u < rem; u++) {         // <=7 iterations
            float4 c0 = pf0[u], c1 = pf1[u];
            float lpv[8] = {c0.x, c0.y, c0.z, c0.w, c1.x, c1.y, c1.z, c1.w};
            float bw = __shfl_sync(0xffffffffu, bt[7], src);
            float bm1_0 = (lane == 0) ? PADV : bw;
            unsigned by = (bw    > bt[0]) ? 1u   : 0u;
            by |= (bt[0] > bt[1]) ? 2u   : 0u;
            by |= (bt[1] > bt[2]) ? 4u   : 0u;
            by |= (bt[2] > bt[3]) ? 8u   : 0u;
            by |= (bt[3] > bt[4]) ? 16u  : 0u;
            by |= (bt[4] > bt[5]) ? 32u  : 0u;
            by |= (bt[5] > bt[6]) ? 64u  : 0u;
            by |= (bt[6] > bt[7]) ? 128u : 0u;
            Db[(size_t)(tb + u - 1) * 32] = (unsigned char)by;
#pragma unroll
            for (int k = 7; k >= 0; k--) {
                float bm1 = (k == 0) ? bm1_0 : bt[k - 1];
                bt[k] = fmaxf(bt[k], bm1) + lpv[k];
            }
        }
    }
}

// ============================================================
// K3: backtrace (R7 simple LDS-chain walk), bounded to k <= ml-1
//   with early exit once r < 0 (absorbing; writes stop anyway).
// ============================================================
__global__ void __launch_bounds__(256) k_bt(const int* __restrict__ tl,
                                            const int* __restrict__ ml) {
    extern __shared__ unsigned char s3raw[];
    unsigned* Dsh = (unsigned*)s3raw;                 // TT*8 words
    int* spath = (int*)(s3raw + TT * 8 * 4);          // TT ints
    int b = blockIdx.x, tid = threadIdx.x;
    const unsigned* Dg = g_D + (size_t)b * TT * 8;
    for (int i = tid; i < TT * 8; i += 256) Dsh[i] = Dg[i];
    for (int i = tid; i < TT; i += 256) spath[i] = -1;
    __syncthreads();

    if (tid == 0) {
        int mlm1v = ml[b] - 1;
        int r = tl[b] - 1;
        spath[mlm1v] = r;                             // k=0 -> t = ml-1
        for (int k = 1; k <= mlm1v; k++) {
            unsigned w = Dsh[(mlm1v - k) * 8 + (r >> 5)];
            int go = (w >> (r & 31)) & 1;             // val_go > val_stay
            r -= go;
            if (r < 0) break;                         // absorbing, spath stays -1
            spath[mlm1v - k] = r;
        }
    }
    __syncthreads();
    for (int i = tid; i < TT; i += 256) g_path[b * TT + i] = spath[i];
}

// ============================================================
// K4: alignment[b][t][l] = (l == path[b][t])  (warp per row)
// ============================================================
__global__ void __launch_bounds__(256) k_align(float* __restrict__ out_align) {
    int gw = (blockIdx.x * 256 + threadIdx.x) >> 5;   // = b*T + t
    int lane = threadIdx.x & 31;
    int p = g_path[gw];
    int base = lane << 3;
    float4 lo = make_float4((float)(p == base),     (float)(p == base + 1),
                            (float)(p == base + 2), (float)(p == base + 3));
    float4 hi = make_float4((float)(p == base + 4), (float)(p == base + 5),
                            (float)(p == base + 6), (float)(p == base + 7));
    float* o = out_align + ((size_t)gw << 8) + base;
    *(float4*)o       = lo;
    *(float4*)(o + 4) = hi;
}

extern "C" void kernel_launch(void* const* d_in, const int* in_sizes, int n_in,
                              void* d_out, int out_size) {
    const float* mlv = (const float*)d_in[0];
    const float* z   = (const float*)d_in[1];
    const int*   tl  = (const int*)d_in[2];
    const int*   ml  = (const int*)d_in[3];

    float* out       = (float*)d_out;
    float* out_loss  = out;                                   // [32]
    float* out_align = out + 32;                              // [32,1600,256]
    float* out_lp    = out + 32 + (size_t)BB * TT * LL;       // [32,256,1600]

    k_prep<<<(BB * LL) / 8, 256>>>(mlv);
    k_probe<<<1, 1>>>();                                      // keeps ncu slot on k_dp
    k_lp<<<dim3(TT / 64, LL / 64, BB), 256>>>(z, out_lp);
    k_dp<<<BB, 64>>>(tl, ml, out_loss);

    int smem_bt = TT * 8 * 4 + TT * 4;                        // 57600 B
    cudaFuncSetAttribute(k_bt, cudaFuncAttributeMaxDynamicSharedMemorySize, smem_bt);
    k_bt<<<BB, 256, smem_bt>>>(tl, ml);

    k_align<<<(BB * TT * 32) / 256, 256>>>(out_align);
}

// round 17
// speedup vs baseline: 3.5323x; 1.2756x over previous
#include <cuda_runtime.h>

#define BB 32
#define LL 256
#define TT 1600
#define KK 80
#define PADV -1.0e12f

// ---- scratch (static device globals; no allocation) ----
__device__ float    g_lpT[BB * TT * LL];     // lp transposed [b][t][l]
__device__ float    g_A[BB * KK * LL];       // GEMM coeffs, k-major [b][k][l]
__device__ float    g_cst[BB * LL];          // per-(b,l) constant
__device__ unsigned g_D[BB * TT * 8];        // Viterbi decision bits, 256/(b,t)
__device__ int      g_path[BB * TT];         // chronological path rows (-1 = none)
__device__ int      g_ready[BB * 25];        // per-(b, t-tile) completion count (4 = ready)
__device__ int      g_probe;                 // dummy sink for k_probe

// ============================================================
// probe: trivial launch so ncu's capture slot stays on k_dp
// ============================================================
__global__ void k_probe() { g_probe = 1; }

// ============================================================
// K0: GEMM coeffs + constant from mu_logvar; also zero flags.
// ============================================================
__global__ void __launch_bounds__(256) k_prep(const float* __restrict__ mlv) {
    if (blockIdx.x == 0) {                     // zero ready flags for this run
        for (int i = threadIdx.x; i < BB * 25; i += 256) g_ready[i] = 0;
    }
    int warp = threadIdx.x >> 5, lane = threadIdx.x & 31;
    int row = blockIdx.x * 8 + warp;           // [0, B*L)
    int b = row >> 8, l = row & 255;
    const float* p = mlv + row * 80;

    float mu = p[lane], lv = p[40 + lane];
    float iv = expf(-lv);
    g_A[(b * KK + lane) * LL + l]      = -0.0125f * iv;
    g_A[(b * KK + 40 + lane) * LL + l] =  0.025f  * mu * iv;
    float acc = mu * mu * iv + lv;
    if (lane < 8) {
        float mu2 = p[32 + lane], lv2 = p[72 + lane];
        float iv2 = expf(-lv2);
        g_A[(b * KK + 32 + lane) * LL + l] = -0.0125f * iv2;
        g_A[(b * KK + 72 + lane) * LL + l] =  0.025f  * mu2 * iv2;
        acc += mu2 * mu2 * iv2 + lv2;
    }
#pragma unroll
    for (int o = 16; o; o >>= 1) acc += __shfl_down_sync(0xffffffffu, acc, o);
    if (!lane) g_cst[row] = -0.0125f * acc;
}

// ============================================================
// K1: lp GEMM (R7 tile), grid reordered b-fastest so t-tiles
//   complete in t-order; signals g_ready[b][ttile] when done.
// ============================================================
__global__ void __launch_bounds__(256) k_lp(const float* __restrict__ z,
                                            float* __restrict__ out_lp) {
    __shared__ float As[80][64];
    __shared__ float Zs[80][64];
    int b = blockIdx.x;                        // b fastest!
    int l0 = blockIdx.y << 6, t0 = blockIdx.z << 6;
    int tid = threadIdx.x;

    for (int i = tid; i < 80 * 64; i += 256)
        As[i >> 6][i & 63] = g_A[(b * KK + (i >> 6)) * LL + l0 + (i & 63)];
    for (int i = tid; i < 40 * 64; i += 256) {
        int c = i >> 6, t = i & 63;
        float zv = z[(b * 40 + c) * TT + t0 + t];
        Zs[c][t] = zv * zv;
        Zs[40 + c][t] = zv;
    }
    __syncthreads();

    int tx = tid & 15, ty = tid >> 4;
    float acc[4][4] = {};
#pragma unroll
    for (int k = 0; k < 80; k++) {
        float4 a  = *(const float4*)&As[k][ty << 2];
        float4 zz = *(const float4*)&Zs[k][tx << 2];
        acc[0][0] += a.x * zz.x; acc[0][1] += a.x * zz.y; acc[0][2] += a.x * zz.z; acc[0][3] += a.x * zz.w;
        acc[1][0] += a.y * zz.x; acc[1][1] += a.y * zz.y; acc[1][2] += a.y * zz.z; acc[1][3] += a.y * zz.w;
        acc[2][0] += a.z * zz.x; acc[2][1] += a.z * zz.y; acc[2][2] += a.z * zz.z; acc[2][3] += a.z * zz.w;
        acc[3][0] += a.w * zz.x; acc[3][1] += a.w * zz.y; acc[3][2] += a.w * zz.z; acc[3][3] += a.w * zz.w;
    }

    float cst[4];
#pragma unroll
    for (int i = 0; i < 4; i++) cst[i] = g_cst[b * LL + l0 + (ty << 2) + i];

#pragma unroll
    for (int i = 0; i < 4; i++) {
        int l = l0 + (ty << 2) + i;
        float4 v = make_float4(acc[i][0] + cst[i], acc[i][1] + cst[i],
                               acc[i][2] + cst[i], acc[i][3] + cst[i]);
        *(float4*)&out_lp[(size_t)(b * LL + l) * TT + t0 + (tx << 2)] = v;
    }
#pragma unroll
    for (int j = 0; j < 4; j++) {
        int t = t0 + (tx << 2) + j;
        float4 v = make_float4(acc[0][j] + cst[0], acc[1][j] + cst[1],
                               acc[2][j] + cst[2], acc[3][j] + cst[3]);
        *(float4*)&g_lpT[(size_t)(b * TT + t) * LL + l0 + (ty << 2)] = v;
    }

    __threadfence();                           // writes visible before flag
    __syncthreads();                           // all threads fenced
    if (tid == 0) atomicAdd(&g_ready[b * 25 + (t0 >> 6)], 1);
}

// ============================================================
// K2: DP, two independent warps per batch, branchless steady
//   state (R15), now consuming lpT tiles as k_lp publishes them
//   (flag spin once per 64-column tile).
// ============================================================
__device__ __forceinline__ float sel8(const float* a, int k) {
    float v = a[0];
#pragma unroll
    for (int i = 1; i < 8; i++) if (i == k) v = a[i];
    return v;
}

__global__ void __launch_bounds__(64) k_dp(const int* __restrict__ tl,
                                           const int* __restrict__ ml,
                                           float* __restrict__ out_loss) {
    int b = blockIdx.x;
    int w = threadIdx.x >> 5, lane = threadIdx.x & 31;
    const float* lp = g_lpT + (size_t)b * TT * LL + (lane << 3);
    const volatile int* vrdy = ((const volatile int*)g_ready) + b * 25;
    int mlm1 = ml[b] - 1;
    int src = (lane + 31) & 31;                 // rotate-up source lane
    int nfull = mlm1 >> 3, rem = mlm1 & 7;

    while (vrdy[0] < 4) {}                      // tile 0 ready
    __threadfence();

    if (w == 0) {
        // ---------------- alpha warp (loss) ----------------
        int tlm1 = tl[b] - 1;
        int rl = tlm1 >> 3, rk = tlm1 & 7;
        float a[8];
#pragma unroll
        for (int k = 0; k < 8; k++) a[k] = PADV;
        if (lane == 0) a[0] = __ldg(g_lpT + (size_t)b * TT * LL);

        float4 pf0[8], pf1[8];
#pragma unroll
        for (int u = 0; u < 8; u++) {           // preload t = 1..8 (tile 0)
            int tc = min(1 + u, TT - 1);
            const float4* p = (const float4*)(lp + (size_t)tc * LL);
            pf0[u] = p[0]; pf1[u] = p[1];
        }

        int cur = 0;
        for (int c = 0; c < nfull; c++) {
            int tb = 1 + (c << 3);
            int need = min(tb + 15, TT - 1) >> 6;
            if (need > cur) {                   // once per 8 chunks
                while (vrdy[need] < 4) {}
                __threadfence();
                cur = need;
            }
#pragma unroll
            for (int u = 0; u < 8; u++) {       // NO conditionals
                float4 c0 = pf0[u], c1 = pf1[u];
                int tp = min(tb + u + 8, TT - 1);
                const float4* p = (const float4*)(lp + (size_t)tp * LL);
                pf0[u] = p[0]; pf1[u] = p[1];
                float lpe[8] = {c0.x + 1e-7f, c0.y + 1e-7f, c0.z + 1e-7f, c0.w + 1e-7f,
                                c1.x + 1e-7f, c1.y + 1e-7f, c1.z + 1e-7f, c1.w + 1e-7f};
                float aw = __shfl_sync(0xffffffffu, a[7], src);
                float am1_0 = (lane == 0) ? PADV : aw;
#pragma unroll
                for (int k = 7; k >= 0; k--) {
                    float am1 = (k == 0) ? am1_0 : a[k - 1];
                    float mx = fmaxf(a[k], am1);
                    float e  = __expf(-fabsf(a[k] - am1));
                    a[k] = mx + (__logf(1.f + e) + lpe[k]);
                }
            }
        }
        for (int u = 0; u < rem; u++) {         // <=7 iterations
            float4 c0 = pf0[u], c1 = pf1[u];
            float lpe[8] = {c0.x + 1e-7f, c0.y + 1e-7f, c0.z + 1e-7f, c0.w + 1e-7f,
                            c1.x + 1e-7f, c1.y + 1e-7f, c1.z + 1e-7f, c1.w + 1e-7f};
            float aw = __shfl_sync(0xffffffffu, a[7], src);
            float am1_0 = (lane == 0) ? PADV : aw;
#pragma unroll
            for (int k = 7; k >= 0; k--) {
                float am1 = (k == 0) ? am1_0 : a[k - 1];
                float mx = fmaxf(a[k], am1);
                float e  = __expf(-fabsf(a[k] - am1));
                a[k] = mx + (__logf(1.f + e) + lpe[k]);
            }
        }
        float rec = sel8(a, rk);                // loop ended exactly at mlm1
        if (lane == rl) out_loss[b] = -rec / (float)(mlm1 + 1);
    } else {
        // ---------------- beta warp (Viterbi D bits) ----------------
        unsigned char* Db = ((unsigned char*)g_D) + (size_t)b * TT * 32 + lane;
        float bt[8];
#pragma unroll
        for (int k = 0; k < 8; k++) bt[k] = PADV;
        if (lane == 0) bt[0] = __ldg(g_lpT + (size_t)b * TT * LL);

        float4 pf0[8], pf1[8];
#pragma unroll
        for (int u = 0; u < 8; u++) {
            int tc = min(1 + u, TT - 1);
            const float4* p = (const float4*)(lp + (size_t)tc * LL);
            pf0[u] = p[0]; pf1[u] = p[1];
        }

        int cur = 0;
        for (int c = 0; c < nfull; c++) {
            int tb = 1 + (c << 3);
            int need = min(tb + 15, TT - 1) >> 6;
            if (need > cur) {
                while (vrdy[need] < 4) {}
                __threadfence();
                cur = need;
            }
#pragma unroll
            for (int u = 0; u < 8; u++) {       // NO conditionals
                float4 c0 = pf0[u], c1 = pf1[u];
                int tp = min(tb + u + 8, TT - 1);
                const float4* p = (const float4*)(lp + (size_t)tp * LL);
                pf0[u] = p[0]; pf1[u] = p[1];
                float lpv[8] = {c0.x, c0.y, c0.z, c0.w, c1.x, c1.y, c1.z, c1.w};

                float bw = __shfl_sync(0xffffffffu, bt[7], src);
                float bm1_0 = (lane == 0) ? PADV : bw;

                unsigned by = (bw    > bt[0]) ? 1u   : 0u;
                by |= (bt[0] > bt[1]) ? 2u   : 0u;
                by |= (bt[1] > bt[2]) ? 4u   : 0u;
                by |= (bt[2] > bt[3]) ? 8u   : 0u;
                by |= (bt[3] > bt[4]) ? 16u  : 0u;
                by |= (bt[4] > bt[5]) ? 32u  : 0u;
                by |= (bt[5] > bt[6]) ? 64u  : 0u;
                by |= (bt[6] > bt[7]) ? 128u : 0u;
                Db[(size_t)(tb + u - 1) * 32] = (unsigned char)by;

#pragma unroll
                for (int k = 7; k >= 0; k--) {
                    float bm1 = (k == 0) ? bm1_0 : bt[k - 1];
                    bt[k] = fmaxf(bt[k], bm1) + lpv[k];
                }
            }
        }
        int tb = 1 + (nfull << 3);
        for (int u = 0; u < rem; u++) {         // <=7 iterations
            float4 c0 = pf0[u], c1 = pf1[u];
            float lpv[8] = {c0.x, c0.y, c0.z, c0.w, c1.x, c1.y, c1.z, c1.w};
            float bw = __shfl_sync(0xffffffffu, bt[7], src);
            float bm1_0 = (lane == 0) ? PADV : bw;
            unsigned by = (bw    > bt[0]) ? 1u   : 0u;
            by |= (bt[0] > bt[1]) ? 2u   : 0u;
            by |= (bt[1] > bt[2]) ? 4u   : 0u;
            by |= (bt[2] > bt[3]) ? 8u   : 0u;
            by |= (bt[3] > bt[4]) ? 16u  : 0u;
            by |= (bt[4] > bt[5]) ? 32u  : 0u;
            by |= (bt[5] > bt[6]) ? 64u  : 0u;
            by |= (bt[6] > bt[7]) ? 128u : 0u;
            Db[(size_t)(tb + u - 1) * 32] = (unsigned char)by;
#pragma unroll
            for (int k = 7; k >= 0; k--) {
                float bm1 = (k == 0) ? bm1_0 : bt[k - 1];
                bt[k] = fmaxf(bt[k], bm1) + lpv[k];
            }
        }
    }
}

// ============================================================
// K3: backtrace (R7 simple LDS-chain walk), bounded to k <= ml-1
//   with early exit once r < 0 (absorbing; writes stop anyway).
// ============================================================
__global__ void __launch_bounds__(256) k_bt(const int* __restrict__ tl,
                                            const int* __restrict__ ml) {
    extern __shared__ unsigned char s3raw[];
    unsigned* Dsh = (unsigned*)s3raw;                 // TT*8 words
    int* spath = (int*)(s3raw + TT * 8 * 4);          // TT ints
    int b = blockIdx.x, tid = threadIdx.x;
    const unsigned* Dg = g_D + (size_t)b * TT * 8;
    for (int i = tid; i < TT * 8; i += 256) Dsh[i] = Dg[i];
    for (int i = tid; i < TT; i += 256) spath[i] = -1;
    __syncthreads();

    if (tid == 0) {
        int mlm1v = ml[b] - 1;
        int r = tl[b] - 1;
        spath[mlm1v] = r;                             // k=0 -> t = ml-1
        for (int k = 1; k <= mlm1v; k++) {
            unsigned w = Dsh[(mlm1v - k) * 8 + (r >> 5)];
            int go = (w >> (r & 31)) & 1;             // val_go > val_stay
            r -= go;
            if (r < 0) break;                         // absorbing, spath stays -1
            spath[mlm1v - k] = r;
        }
    }
    __syncthreads();
    for (int i = tid; i < TT; i += 256) g_path[b * TT + i] = spath[i];
}

// ============================================================
// K4: alignment[b][t][l] = (l == path[b][t])  (warp per row)
// ============================================================
__global__ void __launch_bounds__(256) k_align(float* __restrict__ out_align) {
    int gw = (blockIdx.x * 256 + threadIdx.x) >> 5;   // = b*T + t
    int lane = threadIdx.x & 31;
    int p = g_path[gw];
    int base = lane << 3;
    float4 lo = make_float4((float)(p == base),     (float)(p == base + 1),
                            (float)(p == base + 2), (float)(p == base + 3));
    float4 hi = make_float4((float)(p == base + 4), (float)(p == base + 5),
                            (float)(p == base + 6), (float)(p == base + 7));
    float* o = out_align + ((size_t)gw << 8) + base;
    *(float4*)o       = lo;
    *(float4*)(o + 4) = hi;
}

extern "C" void kernel_launch(void* const* d_in, const int* in_sizes, int n_in,
                              void* d_out, int out_size) {
    const float* mlv = (const float*)d_in[0];
    const float* z   = (const float*)d_in[1];
    const int*   tl  = (const int*)d_in[2];
    const int*   ml  = (const int*)d_in[3];

    float* out       = (float*)d_out;
    float* out_loss  = out;                                   // [32]
    float* out_align = out + 32;                              // [32,1600,256]
    float* out_lp    = out + 32 + (size_t)BB * TT * LL;       // [32,256,1600]

    // fork a side stream so k_dp overlaps k_lp (producer-consumer via g_ready)
    cudaStream_t sB;
    cudaStreamCreateWithFlags(&sB, cudaStreamNonBlocking);
    cudaEvent_t e1, e2;
    cudaEventCreateWithFlags(&e1, cudaEventDisableTiming);
    cudaEventCreateWithFlags(&e2, cudaEventDisableTiming);

    k_prep<<<(BB * LL) / 8, 256>>>(mlv);                      // also zeroes g_ready
    cudaEventRecord(e1, 0);                                   // fork point after k_prep
    k_probe<<<1, 1>>>();                                      // keeps ncu slot aligned

    k_lp<<<dim3(BB, LL / 64, TT / 64), 256>>>(z, out_lp);     // producer (stream 0)

    cudaStreamWaitEvent(sB, e1, 0);
    k_dp<<<BB, 64, 0, sB>>>(tl, ml, out_loss);                // consumer (stream B)
    cudaEventRecord(e2, sB);
    cudaStreamWaitEvent(0, e2, 0);                            // join

    int smem_bt = TT * 8 * 4 + TT * 4;                        // 57600 B
    cudaFuncSetAttribute(k_bt, cudaFuncAttributeMaxDynamicSharedMemorySize, smem_bt);
    k_bt<<<BB, 256, smem_bt>>>(tl, ml);

    k_align<<<(BB * TT * 32) / 256, 256>>>(out_align);
}